// round 2
// baseline (speedup 1.0000x reference)
#include <cuda_runtime.h>
#include <cstdint>

// Linear_60876866453656: out[n, off+w*d+i] = 0.125 * sum_u x[n, off+u*d+i] * W_l[u,w]
// N=262144 rows x 576 f32.  Round-2 design:
//  - lane = row (32 rows/chunk): x LDS.64 delivers unique bytes, no broadcast waste
//  - weights in __constant__ [l][w][u] (scale folded), warp-uniform reads off the crossbar
//  - acc holds all d planes -> 8*d consecutive outputs -> coalescable STG.128
//  - double-buffered smem chunks, persistent grid

static constexpr int ROWS    = 32;      // rows per chunk
static constexpr int THREADS = 256;     // 8 warps; warp w covers columns [w*8, w*8+8)
static constexpr int PS      = 68;      // plane stride (words)
static constexpr int RS1     = 70;      // row strides (words), == 2 mod 4 for 2-wf LDS.64
static constexpr int RS3     = 206;
static constexpr int RS5     = 342;
static constexpr int BUFW    = ROWS * RS5;          // 10944 words
static constexpr int SMEM_BYTES = 2 * BUFW * 4;     // 87552 B

__constant__ float c_wt[3][64][64];   // [l][w][u], pre-scaled by 0.125
__device__   float g_wt[3][64][64];   // staging written by prep kernel

__global__ void prep_kernel(const float* __restrict__ w0,
                            const float* __restrict__ w1,
                            const float* __restrict__ w2) {
    int idx = blockIdx.x * blockDim.x + threadIdx.x;   // 0..4095
    if (idx < 4096) {
        int u = idx >> 6, w = idx & 63;
        g_wt[0][w][u] = 0.125f * w0[idx];
        g_wt[1][w][u] = 0.125f * w1[idx];
        g_wt[2][w][u] = 0.125f * w2[idx];
    }
}

__device__ __forceinline__ void fma2(unsigned long long& d,
                                     unsigned long long a,
                                     unsigned long long b) {
    asm("fma.rn.f32x2 %0, %1, %2, %0;" : "+l"(d) : "l"(a), "l"(b));
}

// Coalesced LDG of one l-block (32 rows x 64*D floats) into registers.
template<int D, int OFF>
__device__ __forceinline__ void do_ldg(float4 (&pref)[10],
                                       const float* __restrict__ x,
                                       int row0, int tid) {
#pragma unroll
    for (int k = 0; k < 2 * D; k++) {
        int q   = tid + THREADS * k;
        int row = q / (16 * D);
        int c4  = q % (16 * D);
        pref[k] = *reinterpret_cast<const float4*>(
            x + (size_t)(row0 + row) * 576 + OFF + c4 * 4);
    }
}

// Transposed store: element p=u*D+i of row -> sm[row*RS + i*PS + u].
template<int D, int RS>
__device__ __forceinline__ void do_sts(const float4 (&pref)[10],
                                       float* __restrict__ sm, int tid) {
#pragma unroll
    for (int k = 0; k < 2 * D; k++) {
        int q   = tid + THREADS * k;
        int row = q / (16 * D);
        int p0  = (q % (16 * D)) * 4;
        const float* pf = reinterpret_cast<const float*>(&pref[k]);
#pragma unroll
        for (int e = 0; e < 4; e++) {
            int p = p0 + e;
            sm[row * RS + (p % D) * PS + (p / D)] = pf[e];
        }
    }
}

template<int D, int OFF, int RS, int L>
__device__ __forceinline__ void do_compute(const float* __restrict__ sm,
                                           float* __restrict__ out,
                                           int row0, int lane, int wid) {
    const int w0 = wid * 8;
    unsigned long long acc[8][D];
#pragma unroll
    for (int j = 0; j < 8; j++)
#pragma unroll
        for (int i = 0; i < D; i++) acc[j][i] = 0ull;

    const unsigned long long* __restrict__ wp =
        reinterpret_cast<const unsigned long long*>(&c_wt[L][w0][0]);  // stride 32 per w
    const float* __restrict__ xs = sm + lane * RS;

#pragma unroll 8
    for (int up = 0; up < 32; up++) {
        unsigned long long xv[D];
#pragma unroll
        for (int i = 0; i < D; i++)
            xv[i] = *reinterpret_cast<const unsigned long long*>(xs + i * PS + 2 * up);
#pragma unroll
        for (int j = 0; j < 8; j++) {
            unsigned long long wv = wp[j * 32 + up];
#pragma unroll
            for (int i = 0; i < D; i++)
                fma2(acc[j][i], xv[i], wv);
        }
    }

    // Epilogue: thread owns out[row, OFF + w0*D .. +8*D) -- contiguous.
    float res[8 * D];
#pragma unroll
    for (int j = 0; j < 8; j++)
#pragma unroll
        for (int i = 0; i < D; i++) {
            float2 a = *reinterpret_cast<float2*>(&acc[j][i]);
            res[j * D + i] = a.x + a.y;           // 0.125 folded into weights
        }

    float* __restrict__ ob = out + (size_t)(row0 + lane) * 576 + OFF + w0 * D;
#pragma unroll
    for (int v = 0; v < 2 * D; v++)
        *reinterpret_cast<float4*>(ob + 4 * v) =
            make_float4(res[4 * v], res[4 * v + 1], res[4 * v + 2], res[4 * v + 3]);
}

__global__ __launch_bounds__(THREADS, 2)
void lin_kernel(const float* __restrict__ x, float* __restrict__ out, int nchunks) {
    extern __shared__ float sm[];
    float* bufA = sm;
    float* bufB = sm + BUFW;

    const int tid  = threadIdx.x;
    const int lane = tid & 31;
    const int wid  = tid >> 5;

    int chunk = blockIdx.x;
    if (chunk >= nchunks) return;

    float4 pref[10];
    float* bw = bufA;

    do_ldg<1, 0>(pref, x, chunk * ROWS, tid);

    while (true) {
        const int row0 = chunk * ROWS;
        int nchunk = chunk + gridDim.x;
        const bool last = (nchunk >= nchunks);
        const int nrow0 = (last ? chunk : nchunk) * ROWS;

        // ---- l=0 (d=1, off=0) ----
        do_sts<1, RS1>(pref, bw, tid);
        __syncthreads();
        do_ldg<3, 64>(pref, x, row0, tid);
        do_compute<1, 0, RS1, 0>(bw, out, row0, lane, wid);
        bw = (bw == bufA) ? bufB : bufA;

        // ---- l=1 (d=3, off=64) ----
        do_sts<3, RS3>(pref, bw, tid);
        __syncthreads();
        do_ldg<5, 256>(pref, x, row0, tid);
        do_compute<3, 64, RS3, 1>(bw, out, row0, lane, wid);
        bw = (bw == bufA) ? bufB : bufA;

        // ---- l=2 (d=5, off=256) ----
        do_sts<5, RS5>(pref, bw, tid);
        __syncthreads();
        do_ldg<1, 0>(pref, x, nrow0, tid);
        do_compute<5, 256, RS5, 2>(bw, out, row0, lane, wid);
        bw = (bw == bufA) ? bufB : bufA;

        if (last) break;
        chunk = nchunk;
    }
}

extern "C" void kernel_launch(void* const* d_in, const int* in_sizes, int n_in,
                              void* d_out, int out_size) {
    const float* x  = (const float*)d_in[0];
    const float* w0 = (const float*)d_in[1];
    const float* w1 = (const float*)d_in[2];
    const float* w2 = (const float*)d_in[3];
    float* out = (float*)d_out;

    int nrows   = in_sizes[0] / 576;
    int nchunks = nrows / ROWS;                       // 262144/32 = 8192

    prep_kernel<<<16, 256>>>(w0, w1, w2);

    void* gptr = nullptr;
    cudaGetSymbolAddress(&gptr, g_wt);
    cudaMemcpyToSymbolAsync(c_wt, gptr, sizeof(float) * 3 * 64 * 64, 0,
                            cudaMemcpyDeviceToDevice, 0);

    cudaFuncSetAttribute(lin_kernel,
                         cudaFuncAttributeMaxDynamicSharedMemorySize, SMEM_BYTES);
    lin_kernel<<<296, THREADS, SMEM_BYTES>>>(x, out, nchunks);
}

// round 4
// speedup vs baseline: 7.7092x; 7.7092x over previous
#include <cuda_runtime.h>
#include <cstdint>

// Linear_60876866453656: out[n, off+w*d+i] = 0.125 * sum_u x[n, off+u*d+i] * W_l[u,w]
// N=262144 rows x 576 f32.
// Design: weights in SMEM (warp-uniform broadcast LDS.128 = 1 wavefront),
// lane=row x reads (conflict-free LDS.128: row strides 68/204/340 mod 32 give
// disjoint bank quads per 8-lane phase), all math as packed fma.rn.f32x2,
// contiguous per-thread outputs -> STG.128 epilogue, persistent 1 CTA/SM.

static constexpr int THREADS = 512;           // 16 warps, 1 CTA/SM
static constexpr int CH      = 64;            // rows per chunk
static constexpr int PS      = 68;            // i-plane stride (words)
static constexpr int W_WORDS = 3 * 64 * 64;   // 12288
static constexpr int B0_OFF  = W_WORDS;
static constexpr int B1_OFF  = B0_OFF + CH * 1 * PS;
static constexpr int B2_OFF  = B1_OFF + CH * 3 * PS;
static constexpr int SMEM_WORDS = B2_OFF + CH * 5 * PS;   // 51456
static constexpr int SMEM_BYTES = SMEM_WORDS * 4;         // 205824 (< 227KB cap)

__device__ __forceinline__ void fma2(unsigned long long& d,
                                     unsigned long long a,
                                     unsigned long long b) {
    asm("fma.rn.f32x2 %0, %1, %2, %0;" : "+l"(d) : "l"(a), "l"(b));
}

// Coalesced float4 LDG of one l-block (CH rows x 64*D floats).
template<int D, int OFF>
__device__ __forceinline__ void do_ldg(float4 (&pref)[2 * D],
                                       const float* __restrict__ x,
                                       int row0, int tid) {
#pragma unroll
    for (int k = 0; k < 2 * D; k++) {
        int q   = tid + THREADS * k;
        int row = q / (16 * D);
        int c4  = q % (16 * D);
        pref[k] = *reinterpret_cast<const float4*>(
            x + (size_t)(row0 + row) * 576 + OFF + 4 * c4);
    }
}

// Transposed store: element p = u*D+i of row -> buf[row*(D*PS) + i*PS + u].
template<int D>
__device__ __forceinline__ void do_sts(const float4 (&pref)[2 * D],
                                       float* __restrict__ buf, int tid) {
#pragma unroll
    for (int k = 0; k < 2 * D; k++) {
        int q   = tid + THREADS * k;
        int row = q / (16 * D);
        int p0  = 4 * (q % (16 * D));
        const float* pf = reinterpret_cast<const float*>(&pref[k]);
#pragma unroll
        for (int e = 0; e < 4; e++) {
            int p = p0 + e;
            buf[row * (D * PS) + (p % D) * PS + (p / D)] = pf[e];
        }
    }
}

template<int D, int OFF>
__device__ __forceinline__ void do_compute(const float* __restrict__ buf,
                                           const float* __restrict__ wsm_l,
                                           float* __restrict__ out,
                                           int row0, int row_local, int w0) {
    unsigned long long acc[8][D];
#pragma unroll
    for (int j = 0; j < 8; j++)
#pragma unroll
        for (int i = 0; i < D; i++) acc[j][i] = 0ull;

    const float* __restrict__ xs = buf + row_local * (D * PS);

#pragma unroll
    for (int up2 = 0; up2 < 16; up2++) {          // covers u = 4*up2 .. 4*up2+3
        ulonglong2 xv[D];
#pragma unroll
        for (int i = 0; i < D; i++)
            xv[i] = *reinterpret_cast<const ulonglong2*>(xs + i * PS + 4 * up2);
#pragma unroll
        for (int j = 0; j < 8; j++) {
            ulonglong2 wv = *reinterpret_cast<const ulonglong2*>(
                wsm_l + (w0 + j) * 64 + 4 * up2);  // uniform broadcast, 1 wf
#pragma unroll
            for (int i = 0; i < D; i++) {
                fma2(acc[j][i], xv[i].x, wv.x);
                fma2(acc[j][i], xv[i].y, wv.y);
            }
        }
    }

    // Thread owns out[row, OFF + w0*D .. +8D) -- contiguous, STG.128.
    float res[8 * D];
#pragma unroll
    for (int j = 0; j < 8; j++)
#pragma unroll
        for (int i = 0; i < D; i++) {
            float2 a = *reinterpret_cast<float2*>(&acc[j][i]);
            res[j * D + i] = a.x + a.y;
        }
    float* __restrict__ ob = out + (size_t)(row0 + row_local) * 576 + OFF + w0 * D;
#pragma unroll
    for (int v = 0; v < 2 * D; v++)
        *reinterpret_cast<float4*>(ob + 4 * v) =
            make_float4(res[4 * v], res[4 * v + 1], res[4 * v + 2], res[4 * v + 3]);
}

__global__ __launch_bounds__(THREADS, 1)
void lin_kernel(const float* __restrict__ x,
                const float* __restrict__ w0,
                const float* __restrict__ w1,
                const float* __restrict__ w2,
                float* __restrict__ out, int nchunks) {
    extern __shared__ float sm[];
    const int tid  = threadIdx.x;
    const int lane = tid & 31;
    const int wid  = tid >> 5;
    const int row_local = ((wid >> 3) << 5) + lane;   // warps 0-7: rows 0-31; 8-15: 32-63
    const int wcol0     = (wid & 7) * 8;              // 8 w-columns per warp

    // Weights -> smem, transposed to [l][w][u], 0.125 folded. One-time cost.
    {
        const float* wsrc[3] = {w0, w1, w2};
        for (int idx = tid; idx < W_WORDS; idx += THREADS) {
            int l = idx >> 12, r = idx & 4095;
            int u = r >> 6, w = r & 63;
            sm[l * 4096 + w * 64 + u] = 0.125f * wsrc[l][r];
        }
    }
    __syncthreads();

    float* b0 = sm + B0_OFF;
    float* b1 = sm + B1_OFF;
    float* b2 = sm + B2_OFF;

    int chunk = blockIdx.x;
    if (chunk >= nchunks) return;

    float4 pref1[2], pref3[6], pref5[10];
    do_ldg<1, 0>(pref1, x, chunk * CH, tid);

    while (true) {
        const int row0 = chunk * CH;
        int nchunk = chunk + gridDim.x;
        const bool last = (nchunk >= nchunks);
        const int nrow0 = (last ? chunk : nchunk) * CH;

        // ---- l=0 (d=1, off=0) ----
        do_sts<1>(pref1, b0, tid);
        __syncthreads();
        do_ldg<3, 64>(pref3, x, row0, tid);
        do_compute<1, 0>(b0, sm, out, row0, row_local, wcol0);

        // ---- l=1 (d=3, off=64) ----
        do_sts<3>(pref3, b1, tid);
        __syncthreads();
        do_ldg<5, 256>(pref5, x, row0, tid);
        do_compute<3, 64>(b1, sm + 4096, out, row0, row_local, wcol0);

        // ---- l=2 (d=5, off=256) ----
        do_sts<5>(pref5, b2, tid);
        __syncthreads();
        do_ldg<1, 0>(pref1, x, nrow0, tid);
        do_compute<5, 256>(b2, sm + 8192, out, row0, row_local, wcol0);

        if (last) break;
        chunk = nchunk;
    }
}

extern "C" void kernel_launch(void* const* d_in, const int* in_sizes, int n_in,
                              void* d_out, int out_size) {
    const float* x  = (const float*)d_in[0];
    const float* w0 = (const float*)d_in[1];
    const float* w1 = (const float*)d_in[2];
    const float* w2 = (const float*)d_in[3];
    float* out = (float*)d_out;

    int nrows   = in_sizes[0] / 576;
    int nchunks = nrows / CH;                       // 262144/64 = 4096

    cudaFuncSetAttribute(lin_kernel,
                         cudaFuncAttributeMaxDynamicSharedMemorySize, SMEM_BYTES);
    lin_kernel<<<148, THREADS, SMEM_BYTES>>>(x, w0, w1, w2, out, nchunks);
}